// round 15
// baseline (speedup 1.0000x reference)
#include <cuda_runtime.h>
#include <cstdint>

#define NN 100000
#define DD 128
#define EE 1600000
#define ND (NN * DD)
#define TM 64
#define NBLK 1563   // ceil(NN / 64)

// ---------------- scratch ----------------
__device__ float g_h[ND];
__device__ float g_agg[ND];
__device__ float g_M[3 * 384 * 128];   // M_l[j][t] = sum_k W_ih[j,k] * W_l[t,k]
__device__ int   g_src[EE];
__device__ int   g_dst[EE];
__device__ int   g_esrc[EE];
__device__ float g_ew[EE];
__device__ int   g_deg[NN];
__device__ int   g_eoff[NN + 1];
__device__ int   g_epos[NN];
__device__ int   g_is64;

// ---------------- f32x2 helpers ----------------
__device__ __forceinline__ unsigned long long pack2(float x, float y) {
    unsigned long long r;
    asm("mov.b64 %0, {%1, %2};" : "=l"(r) : "f"(x), "f"(y));
    return r;
}
__device__ __forceinline__ void fma2(unsigned long long& d, unsigned long long a, unsigned long long b) {
    asm("fma.rn.f32x2 %0, %1, %2, %0;" : "+l"(d) : "l"(a), "l"(b));
}
__device__ __forceinline__ float2 unpack2(unsigned long long v) {
    float2 f;
    asm("mov.b64 {%0, %1}, %2;" : "=f"(f.x), "=f"(f.y) : "l"(v));
    return f;
}
__device__ __forceinline__ float sigm(float x) { return 1.f / (1.f + expf(-x)); }

// ---------------- utility kernels ----------------
__global__ void copy4_kernel(float4* __restrict__ dst, const float4* __restrict__ src, int n4) {
    int i = blockIdx.x * blockDim.x + threadIdx.x;
    if (i < n4) dst[i] = src[i];
}
__global__ void detect_kernel(const unsigned int* __restrict__ p) {
    if (blockIdx.x == 0 && threadIdx.x == 0) {
        unsigned long long s = 0;
        for (int i = 1; i < 2048; i += 2) s += p[i];
        g_is64 = (s == 0ull) ? 1 : 0;
    }
}
__global__ void conv_edges_kernel(const int* __restrict__ p) {
    int i = blockIdx.x * blockDim.x + threadIdx.x;
    if (i >= EE) return;
    if (g_is64) { g_src[i] = p[2 * i]; g_dst[i] = p[2 * (EE + i)]; }
    else        { g_src[i] = p[i];     g_dst[i] = p[EE + i]; }
}

// ---------------- CSR build ----------------
__global__ void zero_deg_kernel() {
    int i = blockIdx.x * blockDim.x + threadIdx.x;
    if (i < NN) g_deg[i] = 0;
}
__global__ void hist_kernel() {
    int i = blockIdx.x * blockDim.x + threadIdx.x;
    if (i < EE) atomicAdd(&g_deg[g_dst[i]], 1);
}
__global__ void scan_kernel() {
    __shared__ int ssum[256];
    int t = threadIdx.x;
    int b = t * 392;
    int e = min(b + 392, NN);
    int s = 0;
    for (int n = b; n < e; n++) s += g_deg[n];
    ssum[t] = s;
    __syncthreads();
    if (t == 0) {
        int run = 0;
        for (int i = 0; i < 256; i++) { int v = ssum[i]; ssum[i] = run; run += v; }
    }
    __syncthreads();
    int run = ssum[t];
    for (int n = b; n < e; n++) {
        g_eoff[n] = run;
        g_epos[n] = run;
        run += g_deg[n];
    }
    if (t == 255) g_eoff[NN] = run;
}
__global__ void fill_kernel(const float* __restrict__ ea) {
    int i = blockIdx.x * blockDim.x + threadIdx.x;
    if (i >= EE) return;
    int d = g_dst[i];
    int slot = atomicAdd(&g_epos[d], 1);
    g_esrc[slot] = g_src[i];
    g_ew[slot] = ea[i];
}

// ---------------- M_l = W_ih @ W_l^T ----------------
__global__ void mcomb_kernel(const float* __restrict__ W, const float* __restrict__ W_ih) {
    int idx = blockIdx.x * blockDim.x + threadIdx.x;
    if (idx >= 384 * 128) return;
    int l = blockIdx.y;
    int j = idx >> 7, t = idx & 127;
    const float* wi = W_ih + j * 128;
    const float* wl = W + l * 128 * 128 + t * 128;
    float s = 0.f;
#pragma unroll 8
    for (int k = 0; k < 128; k++) s = fmaf(__ldg(&wi[k]), __ldg(&wl[k]), s);
    g_M[(l * 384 + j) * 128 + t] = s;
}

// ---------------- gather: agg[n] = sum_{e: dst=n} h[src_e] * w_e (warp per node) ----------------
__global__ void gather_kernel() {
    int gw = (blockIdx.x * blockDim.x + threadIdx.x) >> 5;
    int lane = threadIdx.x & 31;
    if (gw >= NN) return;
    int beg = g_eoff[gw], end = g_eoff[gw + 1];
    float4 acc = make_float4(0.f, 0.f, 0.f, 0.f);
    for (int e = beg; e < end; e++) {
        int s = __ldg(&g_esrc[e]);
        float w = __ldg(&g_ew[e]);
        float4 v = *((const float4*)g_h + (size_t)s * 32 + lane);
        acc.x = fmaf(v.x, w, acc.x);
        acc.y = fmaf(v.y, w, acc.y);
        acc.z = fmaf(v.z, w, acc.z);
        acc.w = fmaf(v.w, w, acc.w);
    }
    *((float4*)g_agg + (size_t)gw * 32 + lane) = acc;
}

// ---------------- one K=128 GEMM pass (M=64 tile): acc += A(64 rows) @ B(128 rows)^T ----------------
// As [16][68] f32, Bsd [16][132] u64 (values pre-duplicated)
__device__ __forceinline__ void gemm_pass64(float* As, unsigned long long* Bsd,
                                            unsigned long long acc[8][2],
                                            const float* __restrict__ Arow,
                                            const float* __restrict__ Brow,
                                            bool aok, int tid, int tx, int ty) {
    const int lma = tid >> 2;            // 0..63  (A row)
    const int l0a = (tid & 3) * 4;       // k offset 0,4,8,12
    const int lmb = tid >> 1;            // 0..127 (B row)
    const int l0b = (tid & 1) * 8;       // k offset 0 or 8

    const float4 z4 = make_float4(0.f, 0.f, 0.f, 0.f);
    float4 a0 = aok ? *(const float4*)&Arow[l0a] : z4;
    float4 b0 = *(const float4*)&Brow[l0b];
    float4 b1 = *(const float4*)&Brow[l0b + 4];

    for (int c = 0; c < 8; c++) {
        __syncthreads();
        As[(l0a + 0) * 68 + lma] = a0.x; As[(l0a + 1) * 68 + lma] = a0.y;
        As[(l0a + 2) * 68 + lma] = a0.z; As[(l0a + 3) * 68 + lma] = a0.w;
        Bsd[(l0b + 0) * 132 + lmb] = pack2(b0.x, b0.x); Bsd[(l0b + 1) * 132 + lmb] = pack2(b0.y, b0.y);
        Bsd[(l0b + 2) * 132 + lmb] = pack2(b0.z, b0.z); Bsd[(l0b + 3) * 132 + lmb] = pack2(b0.w, b0.w);
        Bsd[(l0b + 4) * 132 + lmb] = pack2(b1.x, b1.x); Bsd[(l0b + 5) * 132 + lmb] = pack2(b1.y, b1.y);
        Bsd[(l0b + 6) * 132 + lmb] = pack2(b1.z, b1.z); Bsd[(l0b + 7) * 132 + lmb] = pack2(b1.w, b1.w);
        __syncthreads();

        if (c < 7) {
            int kn = (c + 1) * 16;
            a0 = aok ? *(const float4*)&Arow[kn + l0a] : z4;
            b0 = *(const float4*)&Brow[kn + l0b];
            b1 = *(const float4*)&Brow[kn + l0b + 4];
        }

#pragma unroll
        for (int kk = 0; kk < 16; kk++) {
            ulonglong2 pa = *(const ulonglong2*)&As[kk * 68 + ty * 4];
            unsigned long long ap0 = pa.x, ap1 = pa.y;
#pragma unroll
            for (int jj = 0; jj < 8; jj++) {
                unsigned long long b2 = Bsd[kk * 132 + tx + 16 * jj];
                fma2(acc[jj][0], ap0, b2);
                fma2(acc[jj][1], ap1, b2);
            }
        }
    }
}

// ---------------- fused: h_new = GRU(agg@M^T + b_ih, h@W_hh^T + b_hh, h) ----------------
// SMEM: As 4352 + Bsd 16896 + 2 stages (32 e x 256 tid) f32 = 65536  -> 86784 B => 2 CTAs/SM
#define STG_OFF 21248
#define SMEM_FUSED (21248 + 2 * 32768)   // 86784

__global__ __launch_bounds__(256) void fused_gemm_gru_kernel(const float* __restrict__ Ml,
                                                             const float* __restrict__ W_hh,
                                                             const float* __restrict__ b_ih,
                                                             const float* __restrict__ b_hh,
                                                             float* __restrict__ hout) {
    extern __shared__ char smem[];
    float* As = (float*)smem;
    unsigned long long* Bsd = (unsigned long long*)(smem + 4352);
    float* stg0 = (float*)(smem + STG_OFF);            // r, later n
    float* stg1 = stg0 + 32 * 256;                     // i_n

    const int tid = threadIdx.x;
    const int tx = tid & 15, ty = tid >> 4;            // col = tx + 16*jj; rows = ty*4 + {0..3}
    const int m0 = blockIdx.x * TM;
    const bool aok = (m0 + (tid >> 2)) < NN;

    const float* AggRow = g_agg + (size_t)(m0 + (tid >> 2)) * 128;
    const float* HRow   = g_h   + (size_t)(m0 + (tid >> 2)) * 128;

    unsigned long long acc[8][2];

    // ---- r gate ----
#pragma unroll
    for (int jj = 0; jj < 8; jj++) {
        int col = tx + 16 * jj;
        float bj = __ldg(&b_ih[col]) + __ldg(&b_hh[col]);
        unsigned long long b2 = pack2(bj, bj);
        acc[jj][0] = b2; acc[jj][1] = b2;
    }
    gemm_pass64(As, Bsd, acc, AggRow, Ml   + (size_t)(0 * 128 + (tid >> 1)) * 128, aok, tid, tx, ty);
    gemm_pass64(As, Bsd, acc, HRow,  W_hh + (size_t)(0 * 128 + (tid >> 1)) * 128, aok, tid, tx, ty);
#pragma unroll
    for (int jj = 0; jj < 8; jj++)
#pragma unroll
        for (int p = 0; p < 2; p++) {
            float2 v = unpack2(acc[jj][p]);
            int e = jj * 4 + p * 2;
            stg0[e * 256 + tid] = sigm(v.x);
            stg0[(e + 1) * 256 + tid] = sigm(v.y);
        }

    // ---- i_n ----
#pragma unroll
    for (int jj = 0; jj < 8; jj++) {
        float bj = __ldg(&b_ih[256 + tx + 16 * jj]);
        unsigned long long b2 = pack2(bj, bj);
        acc[jj][0] = b2; acc[jj][1] = b2;
    }
    gemm_pass64(As, Bsd, acc, AggRow, Ml + (size_t)(2 * 128 + (tid >> 1)) * 128, aok, tid, tx, ty);
#pragma unroll
    for (int jj = 0; jj < 8; jj++)
#pragma unroll
        for (int p = 0; p < 2; p++) {
            float2 v = unpack2(acc[jj][p]);
            int e = jj * 4 + p * 2;
            stg1[e * 256 + tid] = v.x;
            stg1[(e + 1) * 256 + tid] = v.y;
        }

    // ---- h_n ; n = tanh(i_n + r * h_n) -> stg0 ----
#pragma unroll
    for (int jj = 0; jj < 8; jj++) {
        float bj = __ldg(&b_hh[256 + tx + 16 * jj]);
        unsigned long long b2 = pack2(bj, bj);
        acc[jj][0] = b2; acc[jj][1] = b2;
    }
    gemm_pass64(As, Bsd, acc, HRow, W_hh + (size_t)(2 * 128 + (tid >> 1)) * 128, aok, tid, tx, ty);
#pragma unroll
    for (int jj = 0; jj < 8; jj++)
#pragma unroll
        for (int p = 0; p < 2; p++) {
            float2 v = unpack2(acc[jj][p]);
            int e = jj * 4 + p * 2;
            float r0 = stg0[e * 256 + tid], r1 = stg0[(e + 1) * 256 + tid];
            stg0[e * 256 + tid]       = tanhf(stg1[e * 256 + tid] + r0 * v.x);
            stg0[(e + 1) * 256 + tid] = tanhf(stg1[(e + 1) * 256 + tid] + r1 * v.y);
        }

    // ---- z gate ----
#pragma unroll
    for (int jj = 0; jj < 8; jj++) {
        int col = 128 + tx + 16 * jj;
        float bj = __ldg(&b_ih[col]) + __ldg(&b_hh[col]);
        unsigned long long b2 = pack2(bj, bj);
        acc[jj][0] = b2; acc[jj][1] = b2;
    }
    gemm_pass64(As, Bsd, acc, AggRow, Ml   + (size_t)(1 * 128 + (tid >> 1)) * 128, aok, tid, tx, ty);
    gemm_pass64(As, Bsd, acc, HRow,  W_hh + (size_t)(1 * 128 + (tid >> 1)) * 128, aok, tid, tx, ty);

    // ---- combine + write (in-place safe: this CTA owns rows [m0, m0+64)) ----
#pragma unroll
    for (int jj = 0; jj < 8; jj++) {
        int col = tx + 16 * jj;
#pragma unroll
        for (int p = 0; p < 2; p++) {
            float2 zv = unpack2(acc[jj][p]);
#pragma unroll
            for (int q = 0; q < 2; q++) {
                int e = jj * 4 + p * 2 + q;
                int row = m0 + ty * 4 + 2 * p + q;
                if (row < NN) {
                    float z = sigm(q ? zv.y : zv.x);
                    float n = stg0[e * 256 + tid];
                    float hv = g_h[(size_t)row * 128 + col];
                    hout[(size_t)row * 128 + col] = (1.f - z) * n + z * hv;
                }
            }
        }
    }
}

// ---------------- launch ----------------
extern "C" void kernel_launch(void* const* d_in, const int* in_sizes, int n_in,
                              void* d_out, int out_size) {
    const float* x    = (const float*)d_in[0];
    const int*   ei   = (const int*)d_in[1];
    const float* ea   = (const float*)d_in[2];
    const float* W    = (const float*)d_in[3];
    const float* W_ih = (const float*)d_in[4];
    const float* W_hh = (const float*)d_in[5];
    const float* b_ih = (const float*)d_in[6];
    const float* b_hh = (const float*)d_in[7];
    float* out = (float*)d_out;

    cudaFuncSetAttribute(fused_gemm_gru_kernel, cudaFuncAttributeMaxDynamicSharedMemorySize, SMEM_FUSED);

    float *ph, *pM;
    cudaGetSymbolAddress((void**)&ph, g_h);
    cudaGetSymbolAddress((void**)&pM, g_M);

    const int n4 = ND / 4;

    detect_kernel<<<1, 32>>>((const unsigned int*)ei);
    conv_edges_kernel<<<EE / 256, 256>>>(ei);
    copy4_kernel<<<n4 / 256, 256>>>((float4*)ph, (const float4*)x, n4);

    zero_deg_kernel<<<(NN + 255) / 256, 256>>>();
    hist_kernel<<<EE / 256, 256>>>();
    scan_kernel<<<1, 256>>>();
    fill_kernel<<<EE / 256, 256>>>(ea);

    mcomb_kernel<<<dim3(192, 3), 256>>>(W, W_ih);

    for (int l = 0; l < 3; l++) {
        gather_kernel<<<(NN * 32 + 255) / 256, 256>>>();
        float* hout = (l == 2) ? out : ph;
        fused_gemm_gru_kernel<<<NBLK, 256, SMEM_FUSED>>>(pM + (size_t)l * 384 * 128, W_hh, b_ih, b_hh, hout);
    }
}